// round 13
// baseline (speedup 1.0000x reference)
#include <cuda_runtime.h>
#include <cuda_fp16.h>
#include <cstdint>

#define SEQ    2048
#define BATCH  4
#define DIMK   2048
#define HEADS  16
#define DHEAD  128
#define ROWS   (BATCH * SEQ) // 8192

// ------------------------- scratch (static, no allocs) ----------------------
__device__ float  g_kv[(size_t)ROWS * 256];      // 8 MB   k(normalized)|v concat
__device__ float  g_m[BATCH * DHEAD * DHEAD];    // 256 KB M = k^T v (fp32)
__device__ __half g_mh[BATCH * DHEAD * DHEAD];   // M^T (fp16, [b][d][k])
__device__ __half g_wqh[(size_t)DIMK * DIMK];    // 8 MB   Wq fp16 [n][k]
__device__ __half g_wkvh[(size_t)256 * DIMK];    // 1 MB   [Wk;Wv] fp16
__device__ float  g_biaskv[256];

typedef unsigned long long u64;

// ------------------------- helpers ------------------------------------------
__device__ __forceinline__ uint32_t smem_u32(const void* p) {
    uint32_t a;
    asm("{ .reg .u64 t; cvta.to.shared.u64 t, %1; cvt.u32.u64 %0, t; }" : "=r"(a) : "l"(p));
    return a;
}
__device__ __forceinline__ void cp_async16(uint32_t saddr, const void* gaddr) {
    asm volatile("cp.async.ca.shared.global [%0], [%1], 16;" :: "r"(saddr), "l"(gaddr));
}
#define CP_COMMIT()  asm volatile("cp.async.commit_group;" ::: "memory")
#define CP_WAIT0()   asm volatile("cp.async.wait_group 0;" ::: "memory")

__device__ __forceinline__ void mma16816(float* c, const uint32_t* a, const uint32_t* b) {
    asm volatile(
        "mma.sync.aligned.m16n8k16.row.col.f32.f16.f16.f32 "
        "{%0,%1,%2,%3}, {%4,%5,%6,%7}, {%8,%9}, {%0,%1,%2,%3};"
        : "+f"(c[0]), "+f"(c[1]), "+f"(c[2]), "+f"(c[3])
        : "r"(a[0]), "r"(a[1]), "r"(a[2]), "r"(a[3]), "r"(b[0]), "r"(b[1]));
}
__device__ __forceinline__ void ldsm_x4(uint32_t* r, uint32_t addr) {
    asm volatile("ldmatrix.sync.aligned.m8n8.x4.shared.b16 {%0,%1,%2,%3}, [%4];"
                 : "=r"(r[0]), "=r"(r[1]), "=r"(r[2]), "=r"(r[3]) : "r"(addr));
}
__device__ __forceinline__ void sts_half8(void* dst, float4 a, float4 b) {
    __half2 h[4];
    h[0] = __floats2half2_rn(a.x, a.y);
    h[1] = __floats2half2_rn(a.z, a.w);
    h[2] = __floats2half2_rn(b.x, b.y);
    h[3] = __floats2half2_rn(b.z, b.w);
    *(uint4*)dst = *(uint4*)h;
}

// ------------------------- weight staging (tiny) -----------------------------
__device__ __forceinline__ void cvt_block(const float* __restrict__ src,
                                          __half* __restrict__ dst, int lb)
{
    size_t idx = ((size_t)lb * 256 + threadIdx.x) * 8;
    float4 x0 = *(const float4*)(src + idx);
    float4 x1 = *(const float4*)(src + idx + 4);
    sts_half8(dst + idx, x0, x1);
}

__global__ void stageWq(const float* __restrict__ Wq)
{
    cvt_block(Wq, g_wqh, blockIdx.x);      // 2048 blocks
}

// blocks [0,128) Wk ; [128,256) Wv ; 256 bias ; [257,321) zero g_m
__global__ void stageWkv(const float* __restrict__ Wk, const float* __restrict__ Wv,
                         const float* __restrict__ bk, const float* __restrict__ bv)
{
    const int bid = blockIdx.x;
    if (bid >= 257) {
        int i = (bid - 257) * 256 + threadIdx.x;
        reinterpret_cast<float4*>(g_m)[i] = make_float4(0.f, 0.f, 0.f, 0.f);
        return;
    }
    if (bid == 256) {
        if (threadIdx.x < 128) {
            g_biaskv[threadIdx.x] = bk[threadIdx.x];
            g_biaskv[threadIdx.x + 128] = bv[threadIdx.x];
        }
        return;
    }
    if (bid < 128) cvt_block(Wk, g_wkvh, bid);
    else           cvt_block(Wv, g_wkvh + (size_t)128 * DIMK, bid - 128);
}

// ------------------------- kv GEMM (inline fp32-A, fused k-l2norm) ----------
// C[m0:m0+128, n0:n0+128] = A32[M x 2048] @ B16[N x 2048]^T + bias  (fp32 out)
#define PITCH 40

__global__ __launch_bounds__(256, 2)
void gemm_kv(const float* __restrict__ A, const __half* __restrict__ B,
             const float* __restrict__ bias, float* __restrict__ Cf,
             int ldc, int normBlocks)
{
    __shared__ __align__(16) __half As[2][128][PITCH];
    __shared__ __align__(16) __half Bs[2][128][PITCH];

    const int tid  = threadIdx.x;
    const int wid  = tid >> 5;
    const int lane = tid & 31;
    const int g    = lane >> 2;
    const int t    = lane & 3;
    const int warp_m = wid & 1;
    const int warp_n = wid >> 1;
    const int m0 = blockIdx.y << 7;
    const int n0 = blockIdx.x << 7;

    const int r0 = tid >> 2;
    const int cH = (tid & 3) << 3;

    const float*  aR0 = A + (size_t)(m0 + r0) * DIMK + cH;
    const float*  aR1 = aR0 + (size_t)64 * DIMK;
    const __half* bR0 = B + (size_t)(n0 + r0) * DIMK + cH;
    const __half* bR1 = bR0 + (size_t)64 * DIMK;

    const int lrow = lane & 15;
    const int lcol = (lane >> 4) << 3;

    float acc[4][4][4];
    #pragma unroll
    for (int i = 0; i < 4; i++)
        #pragma unroll
        for (int j = 0; j < 4; j++)
            #pragma unroll
            for (int k = 0; k < 4; k++) acc[i][j][k] = 0.f;

    {
        float4 p0 = *(const float4*)(aR0);
        float4 p1 = *(const float4*)(aR0 + 4);
        float4 p2 = *(const float4*)(aR1);
        float4 p3 = *(const float4*)(aR1 + 4);
        sts_half8(&As[0][r0][cH], p0, p1);
        sts_half8(&As[0][r0 + 64][cH], p2, p3);
        cp_async16(smem_u32(&Bs[0][r0][cH]), bR0);
        cp_async16(smem_u32(&Bs[0][r0 + 64][cH]), bR1);
        CP_COMMIT();
    }

    const int NT = DIMK / 32;
    const int mb = warp_m << 6;
    const int nb = warp_n << 5;

    for (int it = 0; it < NT; ++it) {
        const int buf = it & 1;
        CP_WAIT0();
        __syncthreads();

        const bool more = (it + 1 < NT);
        float4 p0, p1, p2, p3;
        if (more) {
            const int ko = (it + 1) << 5;
            cp_async16(smem_u32(&Bs[buf ^ 1][r0][cH]), bR0 + ko);
            cp_async16(smem_u32(&Bs[buf ^ 1][r0 + 64][cH]), bR1 + ko);
            CP_COMMIT();
            p0 = *(const float4*)(aR0 + ko);
            p1 = *(const float4*)(aR0 + ko + 4);
            p2 = *(const float4*)(aR1 + ko);
            p3 = *(const float4*)(aR1 + ko + 4);
        }

        #pragma unroll
        for (int ks = 0; ks < 2; ++ks) {
            const int kof = (ks << 4) + lcol;
            uint32_t bf[4][2];
            {
                uint32_t r[4];
                ldsm_x4(r, smem_u32(&Bs[buf][nb + lrow][kof]));
                bf[0][0] = r[0]; bf[1][0] = r[1]; bf[0][1] = r[2]; bf[1][1] = r[3];
                ldsm_x4(r, smem_u32(&Bs[buf][nb + 16 + lrow][kof]));
                bf[2][0] = r[0]; bf[3][0] = r[1]; bf[2][1] = r[2]; bf[3][1] = r[3];
            }
            #pragma unroll
            for (int mt = 0; mt < 4; ++mt) {
                uint32_t af[4];
                ldsm_x4(af, smem_u32(&As[buf][mb + (mt << 4) + lrow][kof]));
                #pragma unroll
                for (int nt = 0; nt < 4; ++nt)
                    mma16816(acc[mt][nt], af, bf[nt]);
            }
        }

        if (more) {
            sts_half8(&As[buf ^ 1][r0][cH], p0, p1);
            sts_half8(&As[buf ^ 1][r0 + 64][cH], p2, p3);
        }
    }
    __syncthreads();

    #pragma unroll
    for (int mt = 0; mt < 4; ++mt) {
        #pragma unroll
        for (int nt = 0; nt < 4; ++nt) {
            const int col = n0 + nb + (nt << 3) + (t << 1);
            const float b0 = bias[col], b1 = bias[col + 1];
            acc[mt][nt][0] += b0; acc[mt][nt][1] += b1;
            acc[mt][nt][2] += b0; acc[mt][nt][3] += b1;
        }
    }

    if (blockIdx.x < (unsigned)normBlocks) {
        float* red = (float*)&As[0][0][0];
        #pragma unroll
        for (int mt = 0; mt < 4; ++mt) {
            float s0 = 0.f, s1 = 0.f;
            #pragma unroll
            for (int nt = 0; nt < 4; ++nt) {
                s0 += acc[mt][nt][0] * acc[mt][nt][0] + acc[mt][nt][1] * acc[mt][nt][1];
                s1 += acc[mt][nt][2] * acc[mt][nt][2] + acc[mt][nt][3] * acc[mt][nt][3];
            }
            s0 += __shfl_xor_sync(0xffffffffu, s0, 1);
            s0 += __shfl_xor_sync(0xffffffffu, s0, 2);
            s1 += __shfl_xor_sync(0xffffffffu, s1, 1);
            s1 += __shfl_xor_sync(0xffffffffu, s1, 2);
            if (t == 0) {
                red[(mb + (mt << 4) + g) * 4 + warp_n]     = s0;
                red[(mb + (mt << 4) + g + 8) * 4 + warp_n] = s1;
            }
        }
        __syncthreads();
        #pragma unroll
        for (int mt = 0; mt < 4; ++mt) {
            const int rl = mb + (mt << 4) + g;
            float ssq0 = red[rl * 4] + red[rl * 4 + 1] + red[rl * 4 + 2] + red[rl * 4 + 3];
            float ssq1 = red[(rl + 8) * 4] + red[(rl + 8) * 4 + 1]
                       + red[(rl + 8) * 4 + 2] + red[(rl + 8) * 4 + 3];
            float inv0 = 1.0f / fmaxf(sqrtf(ssq0), 1e-12f);
            float inv1 = 1.0f / fmaxf(sqrtf(ssq1), 1e-12f);
            #pragma unroll
            for (int nt = 0; nt < 4; ++nt) {
                acc[mt][nt][0] *= inv0; acc[mt][nt][1] *= inv0;
                acc[mt][nt][2] *= inv1; acc[mt][nt][3] *= inv1;
            }
        }
    }

    #pragma unroll
    for (int mt = 0; mt < 4; ++mt) {
        const int row = m0 + mb + (mt << 4) + g;
        #pragma unroll
        for (int nt = 0; nt < 4; ++nt) {
            const int col = n0 + nb + (nt << 3) + (t << 1);
            *(float2*)(Cf + (size_t)row * ldc + col) =
                make_float2(acc[mt][nt][0], acc[mt][nt][1]);
            *(float2*)(Cf + (size_t)(row + 8) * ldc + col) =
                make_float2(acc[mt][nt][2], acc[mt][nt][3]);
        }
    }
}

// ------------------------- fused q GEMM + l2norm + (qn @ M) -> out ----------
// grid (16 heads x, 64 row-tiles y). Dynamic smem pool:
//   phase1: As[2][128][40] @0 (20480B), Bs[2][128][40] @20480
//   phase2: Qs[128][136] @0 (34816B), Ms[128][136] @34816
#define PITCH2 136
#define QPOOL_BYTES (2 * 128 * PITCH2 * 2)   // 69632

__global__ __launch_bounds__(256, 2)
void gemm_q_fused(const float* __restrict__ A, const __half* __restrict__ B,
                  const float* __restrict__ bias, const __half* __restrict__ Mhi,
                  float* __restrict__ Out)
{
    extern __shared__ char pool[];
    __half (*As)[128][PITCH] = (__half(*)[128][PITCH])pool;
    __half (*Bs)[128][PITCH] = (__half(*)[128][PITCH])(pool + 20480);
    __half (*Qs)[PITCH2] = (__half(*)[PITCH2])pool;
    __half (*Ms)[PITCH2] = (__half(*)[PITCH2])(pool + 34816);

    const int tid  = threadIdx.x;
    const int wid  = tid >> 5;
    const int lane = tid & 31;
    const int g    = lane >> 2;
    const int t    = lane & 3;
    const int warp_m = wid & 1;
    const int warp_n = wid >> 1;
    const int h  = blockIdx.x;            // head = 128-col tile of Wq
    const int m0 = blockIdx.y << 7;
    const int n0 = h << 7;
    const int b  = m0 >> 11;

    const int r0 = tid >> 2;
    const int cH = (tid & 3) << 3;

    const float*  aR0 = A + (size_t)(m0 + r0) * DIMK + cH;
    const float*  aR1 = aR0 + (size_t)64 * DIMK;
    const __half* bR0 = B + (size_t)(n0 + r0) * DIMK + cH;
    const __half* bR1 = bR0 + (size_t)64 * DIMK;

    const int lrow = lane & 15;
    const int lcol = (lane >> 4) << 3;

    float acc[4][4][4];
    #pragma unroll
    for (int i = 0; i < 4; i++)
        #pragma unroll
        for (int j = 0; j < 4; j++)
            #pragma unroll
            for (int k = 0; k < 4; k++) acc[i][j][k] = 0.f;

    {
        float4 p0 = *(const float4*)(aR0);
        float4 p1 = *(const float4*)(aR0 + 4);
        float4 p2 = *(const float4*)(aR1);
        float4 p3 = *(const float4*)(aR1 + 4);
        sts_half8(&As[0][r0][cH], p0, p1);
        sts_half8(&As[0][r0 + 64][cH], p2, p3);
        cp_async16(smem_u32(&Bs[0][r0][cH]), bR0);
        cp_async16(smem_u32(&Bs[0][r0 + 64][cH]), bR1);
        CP_COMMIT();
    }

    const int NT = DIMK / 32;
    const int mb = warp_m << 6;
    const int nb = warp_n << 5;

    for (int it = 0; it < NT; ++it) {
        const int buf = it & 1;
        CP_WAIT0();
        __syncthreads();

        const bool more = (it + 1 < NT);
        float4 p0, p1, p2, p3;
        if (more) {
            const int ko = (it + 1) << 5;
            cp_async16(smem_u32(&Bs[buf ^ 1][r0][cH]), bR0 + ko);
            cp_async16(smem_u32(&Bs[buf ^ 1][r0 + 64][cH]), bR1 + ko);
            CP_COMMIT();
            p0 = *(const float4*)(aR0 + ko);
            p1 = *(const float4*)(aR0 + ko + 4);
            p2 = *(const float4*)(aR1 + ko);
            p3 = *(const float4*)(aR1 + ko + 4);
        }

        #pragma unroll
        for (int ks = 0; ks < 2; ++ks) {
            const int kof = (ks << 4) + lcol;
            uint32_t bf[4][2];
            {
                uint32_t r[4];
                ldsm_x4(r, smem_u32(&Bs[buf][nb + lrow][kof]));
                bf[0][0] = r[0]; bf[1][0] = r[1]; bf[0][1] = r[2]; bf[1][1] = r[3];
                ldsm_x4(r, smem_u32(&Bs[buf][nb + 16 + lrow][kof]));
                bf[2][0] = r[0]; bf[3][0] = r[1]; bf[2][1] = r[2]; bf[3][1] = r[3];
            }
            #pragma unroll
            for (int mt = 0; mt < 4; ++mt) {
                uint32_t af[4];
                ldsm_x4(af, smem_u32(&As[buf][mb + (mt << 4) + lrow][kof]));
                #pragma unroll
                for (int nt = 0; nt < 4; ++nt)
                    mma16816(acc[mt][nt], af, bf[nt]);
            }
        }

        if (more) {
            sts_half8(&As[buf ^ 1][r0][cH], p0, p1);
            sts_half8(&As[buf ^ 1][r0 + 64][cH], p2, p3);
        }
    }
    __syncthreads();

    // bias + l2norm (scale 1/sqrt(128))
    #pragma unroll
    for (int mt = 0; mt < 4; ++mt) {
        #pragma unroll
        for (int nt = 0; nt < 4; ++nt) {
            const int col = n0 + nb + (nt << 3) + (t << 1);
            const float b0 = bias[col], b1 = bias[col + 1];
            acc[mt][nt][0] += b0; acc[mt][nt][1] += b1;
            acc[mt][nt][2] += b0; acc[mt][nt][3] += b1;
        }
    }
    {
        float* red = (float*)pool;
        #pragma unroll
        for (int mt = 0; mt < 4; ++mt) {
            float s0 = 0.f, s1 = 0.f;
            #pragma unroll
            for (int nt = 0; nt < 4; ++nt) {
                s0 += acc[mt][nt][0] * acc[mt][nt][0] + acc[mt][nt][1] * acc[mt][nt][1];
                s1 += acc[mt][nt][2] * acc[mt][nt][2] + acc[mt][nt][3] * acc[mt][nt][3];
            }
            s0 += __shfl_xor_sync(0xffffffffu, s0, 1);
            s0 += __shfl_xor_sync(0xffffffffu, s0, 2);
            s1 += __shfl_xor_sync(0xffffffffu, s1, 1);
            s1 += __shfl_xor_sync(0xffffffffu, s1, 2);
            if (t == 0) {
                red[(mb + (mt << 4) + g) * 4 + warp_n]     = s0;
                red[(mb + (mt << 4) + g + 8) * 4 + warp_n] = s1;
            }
        }
        __syncthreads();
        #pragma unroll
        for (int mt = 0; mt < 4; ++mt) {
            const int rl = mb + (mt << 4) + g;
            float ssq0 = red[rl * 4] + red[rl * 4 + 1] + red[rl * 4 + 2] + red[rl * 4 + 3];
            float ssq1 = red[(rl + 8) * 4] + red[(rl + 8) * 4 + 1]
                       + red[(rl + 8) * 4 + 2] + red[(rl + 8) * 4 + 3];
            float inv0 = 0.08838834764831845f / fmaxf(sqrtf(ssq0), 1e-12f);
            float inv1 = 0.08838834764831845f / fmaxf(sqrtf(ssq1), 1e-12f);
            #pragma unroll
            for (int nt = 0; nt < 4; ++nt) {
                acc[mt][nt][0] *= inv0; acc[mt][nt][1] *= inv0;
                acc[mt][nt][2] *= inv1; acc[mt][nt][3] *= inv1;
            }
        }
    }
    __syncthreads();   // red reads done before Qs overwrites pool

    // ---- phase 2: Qs = fp16(qn tile); Ms = M[b]; out_tile = Qs @ Ms ----
    #pragma unroll
    for (int mt = 0; mt < 4; ++mt) {
        const int rl = mb + (mt << 4) + g;
        #pragma unroll
        for (int nt = 0; nt < 4; ++nt) {
            const int cl = nb + (nt << 3) + (t << 1);
            *(__half2*)&Qs[rl][cl]     = __floats2half2_rn(acc[mt][nt][0], acc[mt][nt][1]);
            *(__half2*)&Qs[rl + 8][cl] = __floats2half2_rn(acc[mt][nt][2], acc[mt][nt][3]);
        }
    }
    {
        const __half* mhb = Mhi + (b << 14);
        #pragma unroll
        for (int p = 0; p < 8; ++p) {
            int id = p * 256 + tid;
            int r = id >> 4, cch = (id & 15) << 3;
            *(uint4*)&Ms[r][cch] = *(const uint4*)(mhb + r * 128 + cch);
        }
    }
    __syncthreads();

    float acc2[4][4][4];
    #pragma unroll
    for (int i = 0; i < 4; i++)
        #pragma unroll
        for (int j = 0; j < 4; j++)
            #pragma unroll
            for (int k = 0; k < 4; k++) acc2[i][j][k] = 0.f;

    #pragma unroll
    for (int ks = 0; ks < 8; ++ks) {
        const int kof = (ks << 4) + (t << 1);
        uint32_t bf[4][2];
        #pragma unroll
        for (int nt = 0; nt < 4; ++nt) {
            bf[nt][0] = *(const uint32_t*)&Ms[nb + (nt << 3) + g][kof];
            bf[nt][1] = *(const uint32_t*)&Ms[nb + (nt << 3) + g][kof + 8];
        }
        #pragma unroll
        for (int mt = 0; mt < 4; ++mt) {
            uint32_t af[4];
            af[0] = *(const uint32_t*)&Qs[mb + (mt << 4) + g][kof];
            af[1] = *(const uint32_t*)&Qs[mb + (mt << 4) + g + 8][kof];
            af[2] = *(const uint32_t*)&Qs[mb + (mt << 4) + g][kof + 8];
            af[3] = *(const uint32_t*)&Qs[mb + (mt << 4) + g + 8][kof + 8];
            #pragma unroll
            for (int nt = 0; nt < 4; ++nt)
                mma16816(acc2[mt][nt], af, bf[nt]);
        }
    }

    float* obase = Out + ((size_t)(b * HEADS + h) * SEQ) * DHEAD;
    #pragma unroll
    for (int mt = 0; mt < 4; ++mt) {
        const int nn0 = (m0 + mb + (mt << 4) + g) & (SEQ - 1);
        #pragma unroll
        for (int nt = 0; nt < 4; ++nt) {
            const int d = nb + (nt << 3) + (t << 1);
            *(float2*)(obase + (size_t)nn0 * DHEAD + d) =
                make_float2(acc2[mt][nt][0], acc2[mt][nt][1]);
            *(float2*)(obase + (size_t)(nn0 + 8) * DHEAD + d) =
                make_float2(acc2[mt][nt][2], acc2[mt][nt][3]);
        }
    }
}

// ------------------------- fp32 ktv (64-row chunks) --------------------------
__device__ __forceinline__ u64 pk2(float lo, float hi) {
    u64 r; asm("mov.b64 %0, {%1, %2};" : "=l"(r) : "f"(lo), "f"(hi)); return r;
}
__device__ __forceinline__ float2 upk2(u64 v) {
    float2 r; asm("mov.b64 {%0, %1}, %2;" : "=f"(r.x), "=f"(r.y) : "l"(v)); return r;
}
#define FMA2(acc, a, b) \
    asm("fma.rn.f32x2 %0, %1, %2, %0;" : "+l"(acc) : "l"(a), "l"(b))

__global__ __launch_bounds__(256, 2)
void ktv_kernel(const float* __restrict__ KV, float* __restrict__ Mout)
{
    __shared__ float Ks[16][128];
    __shared__ float Vs[16][128];
    const int tid = threadIdx.x;
    const int tx = tid & 15;
    const int ty = tid >> 4;
    const int b = blockIdx.x;
    const int mbase = b * SEQ + blockIdx.y * 64;
    const float* kp = KV + (size_t)mbase * 256;
    const int lr = tid >> 4;
    const int lc = (tid & 15) << 3;

    u64 acc[8][4];
    #pragma unroll
    for (int i = 0; i < 8; i++)
        #pragma unroll
        for (int j = 0; j < 4; j++) acc[i][j] = 0ull;

    for (int mt = 0; mt < 64; mt += 16) {
        float4 k0 = *(const float4*)(kp + (size_t)(mt + lr) * 256 + lc);
        float4 k1 = *(const float4*)(kp + (size_t)(mt + lr) * 256 + lc + 4);
        float4 v0 = *(const float4*)(kp + 128 + (size_t)(mt + lr) * 256 + lc);
        float4 v1 = *(const float4*)(kp + 128 + (size_t)(mt + lr) * 256 + lc + 4);
        __syncthreads();
        *(float4*)&Ks[lr][lc] = k0; *(float4*)&Ks[lr][lc + 4] = k1;
        *(float4*)&Vs[lr][lc] = v0; *(float4*)&Vs[lr][lc + 4] = v1;
        __syncthreads();
        #pragma unroll
        for (int kk = 0; kk < 16; kk++) {
            float4 af0 = *(const float4*)&Ks[kk][ty << 2];
            float4 af1 = *(const float4*)&Ks[kk][64 + (ty << 2)];
            float4 bf0 = *(const float4*)&Vs[kk][tx << 2];
            float4 bf1 = *(const float4*)&Vs[kk][64 + (tx << 2)];
            u64 b2[4] = {pk2(bf0.x, bf0.y), pk2(bf0.z, bf0.w),
                         pk2(bf1.x, bf1.y), pk2(bf1.z, bf1.w)};
            float av[8] = {af0.x, af0.y, af0.z, af0.w, af1.x, af1.y, af1.z, af1.w};
            #pragma unroll
            for (int i = 0; i < 8; i++) {
                u64 a2 = pk2(av[i], av[i]);
                FMA2(acc[i][0], a2, b2[0]);
                FMA2(acc[i][1], a2, b2[1]);
                FMA2(acc[i][2], a2, b2[2]);
                FMA2(acc[i][3], a2, b2[3]);
            }
        }
    }
    float* Mb = Mout + b * (DHEAD * DHEAD);
    #pragma unroll
    for (int i = 0; i < 8; i++) {
        int row = (i < 4) ? (ty * 4 + i) : (64 + ty * 4 + i - 4);
        #pragma unroll
        for (int jp = 0; jp < 4; jp++) {
            int col = (jp < 2) ? (tx * 4 + jp * 2) : (64 + tx * 4 + (jp - 2) * 2);
            float2 v = upk2(acc[i][jp]);
            atomicAdd(&Mb[row * DHEAD + col],     v.x);
            atomicAdd(&Mb[row * DHEAD + col + 1], v.y);
        }
    }
}

// ------------------------- M split (hi only, transposed) ---------------------
__global__ void splitM(const float* __restrict__ M, __half* __restrict__ Mhi)
{
    int i = blockIdx.x * 256 + threadIdx.x;
    int b = i >> 14;
    int d = (i >> 7) & 127;
    int k = i & 127;
    Mhi[i] = __float2half_rn(M[(b << 14) + (k << 7) + d]);
}

// ---------------------------------------------------------------------------
extern "C" void kernel_launch(void* const* d_in, const int* in_sizes, int n_in,
                              void* d_out, int out_size)
{
    const float* x       = (const float*)d_in[0];
    const float* context = (const float*)d_in[1];
    const float* Wq      = (const float*)d_in[2];
    const float* bq      = (const float*)d_in[3];
    const float* Wk      = (const float*)d_in[4];
    const float* bk      = (const float*)d_in[5];
    const float* Wv      = (const float*)d_in[6];
    const float* bv      = (const float*)d_in[7];
    float* out = (float*)d_out;

    float *kv, *m, *biaskv;
    __half *mh, *wqh, *wkvh;
    cudaGetSymbolAddress((void**)&kv,  g_kv);
    cudaGetSymbolAddress((void**)&m,   g_m);
    cudaGetSymbolAddress((void**)&mh,  g_mh);
    cudaGetSymbolAddress((void**)&wqh, g_wqh);
    cudaGetSymbolAddress((void**)&wkvh, g_wkvh);
    cudaGetSymbolAddress((void**)&biaskv, g_biaskv);

    cudaFuncSetAttribute(gemm_q_fused, cudaFuncAttributeMaxDynamicSharedMemorySize, QPOOL_BYTES);

    // fork/join resources (host-side objects, created during capture)
    cudaStream_t sB;
    cudaStreamCreateWithFlags(&sB, cudaStreamNonBlocking);
    cudaEvent_t evFork, evB;
    cudaEventCreateWithFlags(&evFork, cudaEventDisableTiming);
    cudaEventCreateWithFlags(&evB, cudaEventDisableTiming);

    cudaEventRecord(evFork, 0);
    cudaStreamWaitEvent(sB, evFork, 0);

    // ---- branch B (side stream): weights+zero -> kv gemm -> ktv -> splitM
    stageWkv<<<321, 256, 0, sB>>>(Wk, Wv, bk, bv);
    gemm_kv<<<dim3(2, ROWS / 128), 256, 0, sB>>>(
        context, wkvh, biaskv, kv, 256, 1);
    ktv_kernel<<<dim3(BATCH, 32), 256, 0, sB>>>(kv, m);
    splitM<<<256, 256, 0, sB>>>(m, mh);
    cudaEventRecord(evB, sB);

    // ---- branch A (origin): stage Wq (overlapped with branch B)
    stageWq<<<2048, 256>>>(Wq);

    // ---- join (M ready), then fused q-proj + l2norm + (qn @ M) -> out
    cudaStreamWaitEvent(0, evB, 0);
    gemm_q_fused<<<dim3(HEADS, ROWS / 128), 256, QPOOL_BYTES>>>(
        x, wqh, bq, mh, out);
}

// round 14
// speedup vs baseline: 1.8082x; 1.8082x over previous
#include <cuda_runtime.h>
#include <cuda_fp16.h>
#include <cstdint>

#define SEQ    2048
#define BATCH  4
#define DIMK   2048
#define HEADS  16
#define DHEAD  128
#define ROWS   (BATCH * SEQ) // 8192

// ------------------------- scratch (static, no allocs) ----------------------
__device__ __half g_qh[(size_t)ROWS * DIMK];     // 32 MB  normalized q (fp16)
__device__ float  g_kv[(size_t)ROWS * 256];      // 8 MB   k(normalized)|v concat
__device__ float  g_m[BATCH * DHEAD * DHEAD];    // 256 KB M = k^T v (fp32)
__device__ __half g_mh[BATCH * DHEAD * DHEAD];   // M^T (fp16, [b][d][k])
__device__ __half g_xh[(size_t)ROWS * DIMK];     // 32 MB  x in fp16
__device__ __half g_ch[(size_t)ROWS * DIMK];     // 32 MB  context in fp16
__device__ __half g_wqh[(size_t)DIMK * DIMK];    // 8 MB   Wq fp16 [n][k]
__device__ __half g_wkvh[(size_t)256 * DIMK];    // 1 MB   [Wk;Wv] fp16
__device__ float  g_biaskv[256];

typedef unsigned long long u64;

// ------------------------- helpers ------------------------------------------
__device__ __forceinline__ uint32_t smem_u32(const void* p) {
    uint32_t a;
    asm("{ .reg .u64 t; cvta.to.shared.u64 t, %1; cvt.u32.u64 %0, t; }" : "=r"(a) : "l"(p));
    return a;
}
__device__ __forceinline__ void cp_async16(uint32_t saddr, const void* gaddr) {
    asm volatile("cp.async.ca.shared.global [%0], [%1], 16;" :: "r"(saddr), "l"(gaddr));
}
#define CP_COMMIT()  asm volatile("cp.async.commit_group;" ::: "memory")
#define CP_WAIT(n)   asm volatile("cp.async.wait_group %0;" :: "n"(n) : "memory")

__device__ __forceinline__ void mma16816(float* c, const uint32_t* a, const uint32_t* b) {
    asm volatile(
        "mma.sync.aligned.m16n8k16.row.col.f32.f16.f16.f32 "
        "{%0,%1,%2,%3}, {%4,%5,%6,%7}, {%8,%9}, {%0,%1,%2,%3};"
        : "+f"(c[0]), "+f"(c[1]), "+f"(c[2]), "+f"(c[3])
        : "r"(a[0]), "r"(a[1]), "r"(a[2]), "r"(a[3]), "r"(b[0]), "r"(b[1]));
}
__device__ __forceinline__ void ldsm_x4(uint32_t* r, uint32_t addr) {
    asm volatile("ldmatrix.sync.aligned.m8n8.x4.shared.b16 {%0,%1,%2,%3}, [%4];"
                 : "=r"(r[0]), "=r"(r[1]), "=r"(r[2]), "=r"(r[3]) : "r"(addr));
}

// ------------------------- fused staging kernel ------------------------------
__global__ void tohalf_all(const float* __restrict__ x, const float* __restrict__ ctx,
                           const float* __restrict__ Wq, const float* __restrict__ Wk,
                           const float* __restrict__ Wv, const float* __restrict__ bk,
                           const float* __restrict__ bv)
{
    const int bid = blockIdx.x;
    if (bid == 18688) {
        if (threadIdx.x < 128) {
            g_biaskv[threadIdx.x] = bk[threadIdx.x];
            g_biaskv[threadIdx.x + 128] = bv[threadIdx.x];
        }
        return;
    }
    const float* src;
    __half* dst;
    int lb;
    if (bid < 8192)        { src = x;   dst = g_xh;  lb = bid; }
    else if (bid < 16384)  { src = ctx; dst = g_ch;  lb = bid - 8192; }
    else if (bid < 18432)  { src = Wq;  dst = g_wqh; lb = bid - 16384; }
    else if (bid < 18560)  { src = Wk;  dst = g_wkvh; lb = bid - 18432; }
    else                   { src = Wv;  dst = g_wkvh + (size_t)128 * DIMK; lb = bid - 18560; }
    size_t idx = ((size_t)lb * 256 + threadIdx.x) * 8;
    float4 x0 = *(const float4*)(src + idx);
    float4 x1 = *(const float4*)(src + idx + 4);
    __half2 h[4];
    h[0] = __floats2half2_rn(x0.x, x0.y);
    h[1] = __floats2half2_rn(x0.z, x0.w);
    h[2] = __floats2half2_rn(x1.x, x1.y);
    h[3] = __floats2half2_rn(x1.z, x1.w);
    *(uint4*)(dst + idx) = *(uint4*)h;
}

// ------------------------- HMMA fp16 GEMM + fused row-l2norm ----------------
// R5/R8 proven configuration: 2-stage cp.async.ca, static smem, PITCH 40,
// warp tile 64x32, ldmatrix, occupancy 2.
#define PITCH 40

__global__ __launch_bounds__(256, 2)
void gemm_f16(const __half* __restrict__ A, const __half* __restrict__ B,
              const float* __restrict__ bias, float* __restrict__ Cf,
              __half* __restrict__ Ch, int ldc, int normBlocks, float normScale)
{
    __shared__ __align__(16) __half As[2][128][PITCH];
    __shared__ __align__(16) __half Bs[2][128][PITCH];

    const int tid  = threadIdx.x;
    const int wid  = tid >> 5;
    const int lane = tid & 31;
    const int g    = lane >> 2;
    const int t    = lane & 3;
    const int warp_m = wid & 1;     // 64 rows
    const int warp_n = wid >> 1;    // 32 cols
    const int m0 = blockIdx.y << 7;
    const int n0 = blockIdx.x << 7;

    const __half* aBase = A + (size_t)m0 * DIMK;
    const __half* bBase = B + (size_t)n0 * DIMK;

    const int r0 = tid >> 2,          c0 = (tid & 3) << 3;
    const int r1 = (tid + 256) >> 2,  c1 = c0;

    const int lrow = lane & 15;
    const int lcol = (lane >> 4) << 3;

    float acc[4][4][4];
    #pragma unroll
    for (int i = 0; i < 4; i++)
        #pragma unroll
        for (int j = 0; j < 4; j++)
            #pragma unroll
            for (int k = 0; k < 4; k++) acc[i][j][k] = 0.f;

    cp_async16(smem_u32(&As[0][r0][c0]), aBase + (size_t)r0 * DIMK + c0);
    cp_async16(smem_u32(&As[0][r1][c1]), aBase + (size_t)r1 * DIMK + c1);
    cp_async16(smem_u32(&Bs[0][r0][c0]), bBase + (size_t)r0 * DIMK + c0);
    cp_async16(smem_u32(&Bs[0][r1][c1]), bBase + (size_t)r1 * DIMK + c1);
    CP_COMMIT();

    const int NT = DIMK / 32;   // 64
    const int mb = warp_m << 6;
    const int nb = warp_n << 5;

    for (int it = 0; it < NT; ++it) {
        const int buf = it & 1;
        if (it + 1 < NT) {
            const int nbuf = buf ^ 1;
            const int ko = (it + 1) << 5;
            cp_async16(smem_u32(&As[nbuf][r0][c0]), aBase + (size_t)r0 * DIMK + ko + c0);
            cp_async16(smem_u32(&As[nbuf][r1][c1]), aBase + (size_t)r1 * DIMK + ko + c1);
            cp_async16(smem_u32(&Bs[nbuf][r0][c0]), bBase + (size_t)r0 * DIMK + ko + c0);
            cp_async16(smem_u32(&Bs[nbuf][r1][c1]), bBase + (size_t)r1 * DIMK + ko + c1);
            CP_COMMIT();
            CP_WAIT(1);
        } else {
            CP_WAIT(0);
        }
        __syncthreads();

        #pragma unroll
        for (int ks = 0; ks < 2; ++ks) {
            const int kof = (ks << 4) + lcol;
            uint32_t bf[4][2];
            {
                uint32_t r[4];
                ldsm_x4(r, smem_u32(&Bs[buf][nb + lrow][kof]));
                bf[0][0] = r[0]; bf[1][0] = r[1]; bf[0][1] = r[2]; bf[1][1] = r[3];
                ldsm_x4(r, smem_u32(&Bs[buf][nb + 16 + lrow][kof]));
                bf[2][0] = r[0]; bf[3][0] = r[1]; bf[2][1] = r[2]; bf[3][1] = r[3];
            }
            #pragma unroll
            for (int mt = 0; mt < 4; ++mt) {
                uint32_t af[4];
                ldsm_x4(af, smem_u32(&As[buf][mb + (mt << 4) + lrow][kof]));
                #pragma unroll
                for (int nt = 0; nt < 4; ++nt)
                    mma16816(acc[mt][nt], af, bf[nt]);
            }
        }
        __syncthreads();
    }

    // ---- epilogue: +bias, optional row l2norm, write fp16 or fp32 ----
    #pragma unroll
    for (int mt = 0; mt < 4; ++mt) {
        #pragma unroll
        for (int nt = 0; nt < 4; ++nt) {
            const int col = n0 + nb + (nt << 3) + (t << 1);
            const float b0 = bias[col], b1 = bias[col + 1];
            acc[mt][nt][0] += b0; acc[mt][nt][1] += b1;
            acc[mt][nt][2] += b0; acc[mt][nt][3] += b1;
        }
    }

    if (blockIdx.x < (unsigned)normBlocks) {
        float* red = (float*)&As[0][0][0];
        #pragma unroll
        for (int mt = 0; mt < 4; ++mt) {
            float s0 = 0.f, s1 = 0.f;
            #pragma unroll
            for (int nt = 0; nt < 4; ++nt) {
                s0 += acc[mt][nt][0] * acc[mt][nt][0] + acc[mt][nt][1] * acc[mt][nt][1];
                s1 += acc[mt][nt][2] * acc[mt][nt][2] + acc[mt][nt][3] * acc[mt][nt][3];
            }
            s0 += __shfl_xor_sync(0xffffffffu, s0, 1);
            s0 += __shfl_xor_sync(0xffffffffu, s0, 2);
            s1 += __shfl_xor_sync(0xffffffffu, s1, 1);
            s1 += __shfl_xor_sync(0xffffffffu, s1, 2);
            if (t == 0) {
                red[(mb + (mt << 4) + g) * 4 + warp_n]     = s0;
                red[(mb + (mt << 4) + g + 8) * 4 + warp_n] = s1;
            }
        }
        __syncthreads();
        #pragma unroll
        for (int mt = 0; mt < 4; ++mt) {
            const int rl = mb + (mt << 4) + g;
            float ssq0 = red[rl * 4] + red[rl * 4 + 1] + red[rl * 4 + 2] + red[rl * 4 + 3];
            float ssq1 = red[(rl + 8) * 4] + red[(rl + 8) * 4 + 1]
                       + red[(rl + 8) * 4 + 2] + red[(rl + 8) * 4 + 3];
            float inv0 = normScale / fmaxf(sqrtf(ssq0), 1e-12f);
            float inv1 = normScale / fmaxf(sqrtf(ssq1), 1e-12f);
            #pragma unroll
            for (int nt = 0; nt < 4; ++nt) {
                acc[mt][nt][0] *= inv0; acc[mt][nt][1] *= inv0;
                acc[mt][nt][2] *= inv1; acc[mt][nt][3] *= inv1;
            }
        }
    }

    #pragma unroll
    for (int mt = 0; mt < 4; ++mt) {
        const int row = m0 + mb + (mt << 4) + g;
        #pragma unroll
        for (int nt = 0; nt < 4; ++nt) {
            const int col = n0 + nb + (nt << 3) + (t << 1);
            if (Ch) {
                *(__half2*)(Ch + (size_t)row * ldc + col) =
                    __floats2half2_rn(acc[mt][nt][0], acc[mt][nt][1]);
                *(__half2*)(Ch + (size_t)(row + 8) * ldc + col) =
                    __floats2half2_rn(acc[mt][nt][2], acc[mt][nt][3]);
            } else {
                *(float2*)(Cf + (size_t)row * ldc + col) =
                    make_float2(acc[mt][nt][0], acc[mt][nt][1]);
                *(float2*)(Cf + (size_t)(row + 8) * ldc + col) =
                    make_float2(acc[mt][nt][2], acc[mt][nt][3]);
            }
        }
    }
}

// ------------------------- fp32 ktv (64-row chunks) --------------------------
__device__ __forceinline__ u64 pk2(float lo, float hi) {
    u64 r; asm("mov.b64 %0, {%1, %2};" : "=l"(r) : "f"(lo), "f"(hi)); return r;
}
__device__ __forceinline__ float2 upk2(u64 v) {
    float2 r; asm("mov.b64 {%0, %1}, %2;" : "=f"(r.x), "=f"(r.y) : "l"(v)); return r;
}
#define FMA2(acc, a, b) \
    asm("fma.rn.f32x2 %0, %1, %2, %0;" : "+l"(acc) : "l"(a), "l"(b))

__global__ void zero_m()
{
    int i = blockIdx.x * blockDim.x + threadIdx.x;
    reinterpret_cast<float4*>(g_m)[i] = make_float4(0.f, 0.f, 0.f, 0.f);
}

__global__ __launch_bounds__(256, 2)
void ktv_kernel(const float* __restrict__ KV, float* __restrict__ Mout)
{
    __shared__ float Ks[16][128];
    __shared__ float Vs[16][128];
    const int tid = threadIdx.x;
    const int tx = tid & 15;
    const int ty = tid >> 4;
    const int b = blockIdx.x;
    const int mbase = b * SEQ + blockIdx.y * 64;
    const float* kp = KV + (size_t)mbase * 256;
    const int lr = tid >> 4;
    const int lc = (tid & 15) << 3;

    u64 acc[8][4];
    #pragma unroll
    for (int i = 0; i < 8; i++)
        #pragma unroll
        for (int j = 0; j < 4; j++) acc[i][j] = 0ull;

    for (int mt = 0; mt < 64; mt += 16) {
        float4 k0 = *(const float4*)(kp + (size_t)(mt + lr) * 256 + lc);
        float4 k1 = *(const float4*)(kp + (size_t)(mt + lr) * 256 + lc + 4);
        float4 v0 = *(const float4*)(kp + 128 + (size_t)(mt + lr) * 256 + lc);
        float4 v1 = *(const float4*)(kp + 128 + (size_t)(mt + lr) * 256 + lc + 4);
        __syncthreads();
        *(float4*)&Ks[lr][lc] = k0; *(float4*)&Ks[lr][lc + 4] = k1;
        *(float4*)&Vs[lr][lc] = v0; *(float4*)&Vs[lr][lc + 4] = v1;
        __syncthreads();
        #pragma unroll
        for (int kk = 0; kk < 16; kk++) {
            float4 af0 = *(const float4*)&Ks[kk][ty << 2];
            float4 af1 = *(const float4*)&Ks[kk][64 + (ty << 2)];
            float4 bf0 = *(const float4*)&Vs[kk][tx << 2];
            float4 bf1 = *(const float4*)&Vs[kk][64 + (tx << 2)];
            u64 b2[4] = {pk2(bf0.x, bf0.y), pk2(bf0.z, bf0.w),
                         pk2(bf1.x, bf1.y), pk2(bf1.z, bf1.w)};
            float av[8] = {af0.x, af0.y, af0.z, af0.w, af1.x, af1.y, af1.z, af1.w};
            #pragma unroll
            for (int i = 0; i < 8; i++) {
                u64 a2 = pk2(av[i], av[i]);
                FMA2(acc[i][0], a2, b2[0]);
                FMA2(acc[i][1], a2, b2[1]);
                FMA2(acc[i][2], a2, b2[2]);
                FMA2(acc[i][3], a2, b2[3]);
            }
        }
    }
    float* Mb = Mout + b * (DHEAD * DHEAD);
    #pragma unroll
    for (int i = 0; i < 8; i++) {
        int row = (i < 4) ? (ty * 4 + i) : (64 + ty * 4 + i - 4);
        #pragma unroll
        for (int jp = 0; jp < 4; jp++) {
            int col = (jp < 2) ? (tx * 4 + jp * 2) : (64 + tx * 4 + (jp - 2) * 2);
            float2 v = upk2(acc[i][jp]);
            atomicAdd(&Mb[row * DHEAD + col],     v.x);
            atomicAdd(&Mb[row * DHEAD + col + 1], v.y);
        }
    }
}

// ------------------------- M split (hi only, transposed) ---------------------
__global__ void splitM(const float* __restrict__ M, __half* __restrict__ Mhi)
{
    int i = blockIdx.x * 256 + threadIdx.x;
    int b = i >> 14;
    int d = (i >> 7) & 127;
    int k = i & 127;
    Mhi[i] = __float2half_rn(M[(b << 14) + (k << 7) + d]);
}

// ------------------------- out = q16 @ Mh (single pass) ----------------------
#define PITCH2 136
#define QM_AS_BYTES (128 * PITCH2 * 2)
#define QM_SMEM (2 * QM_AS_BYTES)

__global__ __launch_bounds__(256)
void gemm_qm16(const __half* __restrict__ Q, const __half* __restrict__ Mhi,
               float* __restrict__ Out)
{
    extern __shared__ char dsm[];
    __half (*As)[PITCH2] = (__half(*)[PITCH2])dsm;
    __half (*Bs)[PITCH2] = (__half(*)[PITCH2])(dsm + QM_AS_BYTES);

    const int tid  = threadIdx.x;
    const int wid  = tid >> 5;
    const int lane = tid & 31;
    const int g    = lane >> 2;
    const int t    = lane & 3;
    const int warp_m = wid & 1;
    const int warp_n = wid >> 1;
    const int m0 = blockIdx.x << 7;
    const int h  = blockIdx.y;
    const int b  = m0 >> 11;

    const __half* qBase = Q + (size_t)m0 * DIMK + h * DHEAD;
    const __half* mh = Mhi + (b << 14);

    #pragma unroll
    for (int p = 0; p < 8; ++p) {
        int id = p * 256 + tid;
        int r = id >> 4, cch = (id & 15) << 3;
        *(uint4*)&As[r][cch] = *(const uint4*)(qBase + (size_t)r * DIMK + cch);
        *(uint4*)&Bs[r][cch] = *(const uint4*)(mh + r * 128 + cch);
    }
    __syncthreads();

    float acc[4][4][4];
    #pragma unroll
    for (int i = 0; i < 4; i++)
        #pragma unroll
        for (int j = 0; j < 4; j++)
            #pragma unroll
            for (int k = 0; k < 4; k++) acc[i][j][k] = 0.f;

    const int mb = warp_m << 6;
    const int nb = warp_n << 5;

    #pragma unroll
    for (int ks = 0; ks < 8; ++ks) {
        const int kof = (ks << 4) + (t << 1);
        uint32_t bf[4][2];
        #pragma unroll
        for (int nt = 0; nt < 4; ++nt) {
            bf[nt][0] = *(const uint32_t*)&Bs[nb + (nt << 3) + g][kof];
            bf[nt][1] = *(const uint32_t*)&Bs[nb + (nt << 3) + g][kof + 8];
        }
        #pragma unroll
        for (int mt = 0; mt < 4; ++mt) {
            uint32_t af[4];
            af[0] = *(const uint32_t*)&As[mb + (mt << 4) + g][kof];
            af[1] = *(const uint32_t*)&As[mb + (mt << 4) + g + 8][kof];
            af[2] = *(const uint32_t*)&As[mb + (mt << 4) + g][kof + 8];
            af[3] = *(const uint32_t*)&As[mb + (mt << 4) + g + 8][kof + 8];
            #pragma unroll
            for (int nt = 0; nt < 4; ++nt)
                mma16816(acc[mt][nt], af, bf[nt]);
        }
    }

    float* obase = Out + ((size_t)(b * HEADS + h) * SEQ) * DHEAD;
    #pragma unroll
    for (int mt = 0; mt < 4; ++mt) {
        const int nn0 = (m0 + mb + (mt << 4) + g) & (SEQ - 1);
        #pragma unroll
        for (int nt = 0; nt < 4; ++nt) {
            const int d = nb + (nt << 3) + (t << 1);
            *(float2*)(obase + (size_t)nn0 * DHEAD + d) =
                make_float2(acc[mt][nt][0], acc[mt][nt][1]);
            *(float2*)(obase + (size_t)(nn0 + 8) * DHEAD + d) =
                make_float2(acc[mt][nt][2], acc[mt][nt][3]);
        }
    }
}

// ---------------------------------------------------------------------------
extern "C" void kernel_launch(void* const* d_in, const int* in_sizes, int n_in,
                              void* d_out, int out_size)
{
    const float* x       = (const float*)d_in[0];
    const float* context = (const float*)d_in[1];
    const float* Wq      = (const float*)d_in[2];
    const float* bq      = (const float*)d_in[3];
    const float* Wk      = (const float*)d_in[4];
    const float* bk      = (const float*)d_in[5];
    const float* Wv      = (const float*)d_in[6];
    const float* bv      = (const float*)d_in[7];
    float* out = (float*)d_out;

    float *kv, *m, *biaskv;
    __half *qh, *mh, *xh, *ch, *wqh, *wkvh;
    cudaGetSymbolAddress((void**)&qh,  g_qh);
    cudaGetSymbolAddress((void**)&kv,  g_kv);
    cudaGetSymbolAddress((void**)&m,   g_m);
    cudaGetSymbolAddress((void**)&mh,  g_mh);
    cudaGetSymbolAddress((void**)&xh,  g_xh);
    cudaGetSymbolAddress((void**)&ch,  g_ch);
    cudaGetSymbolAddress((void**)&wqh, g_wqh);
    cudaGetSymbolAddress((void**)&wkvh, g_wkvh);
    cudaGetSymbolAddress((void**)&biaskv, g_biaskv);

    cudaFuncSetAttribute(gemm_qm16, cudaFuncAttributeMaxDynamicSharedMemorySize, QM_SMEM);

    // fork/join resources (host-side objects; created per capture call,
    // intentionally not destroyed while the capture references them)
    cudaStream_t sB;
    cudaStreamCreateWithFlags(&sB, cudaStreamNonBlocking);
    cudaEvent_t evStage, evB;
    cudaEventCreateWithFlags(&evStage, cudaEventDisableTiming);
    cudaEventCreateWithFlags(&evB, cudaEventDisableTiming);

    // 1) fused staging (origin stream)
    tohalf_all<<<18689, 256>>>(x, context, Wq, Wk, Wv, bk, bv);
    cudaEventRecord(evStage, 0);

    // ---- branch B (side stream): kv -> zero -> ktv -> splitM ----
    cudaStreamWaitEvent(sB, evStage, 0);
    gemm_f16<<<dim3(2, ROWS / 128), 256, 0, sB>>>(
        ch, wkvh, biaskv, kv, nullptr, 256, 1, 1.0f);
    zero_m<<<64, 256, 0, sB>>>();
    ktv_kernel<<<dim3(BATCH, 32), 256, 0, sB>>>(kv, m);
    splitM<<<256, 256, 0, sB>>>(m, mh);
    cudaEventRecord(evB, sB);

    // ---- branch A (origin stream): q projection + fused l2norm ----
    gemm_f16<<<dim3(DIMK / 128, ROWS / 128), 256>>>(
        xh, wqh, bq, nullptr, qh, DIMK, 16, 0.08838834764831845f);

    // ---- join, then Out = Qn @ M[b] ----
    cudaStreamWaitEvent(0, evB, 0);
    gemm_qm16<<<dim3(ROWS / 128, HEADS), 256, QM_SMEM>>>(qh, mh, out);
}

// round 16
// speedup vs baseline: 1.8449x; 1.0203x over previous
#include <cuda_runtime.h>
#include <cuda_fp16.h>
#include <cstdint>

#define SEQ    2048
#define BATCH  4
#define DIMK   2048
#define HEADS  16
#define DHEAD  128
#define ROWS   (BATCH * SEQ) // 8192

// ------------------------- scratch (static, no allocs) ----------------------
__device__ __half g_qh[(size_t)ROWS * DIMK];     // 32 MB  normalized q (fp16)
__device__ float  g_kv[(size_t)ROWS * 256];      // 8 MB   k(normalized)|v concat
__device__ float  g_m[BATCH * DHEAD * DHEAD];    // 256 KB M = k^T v (fp32)
__device__ __half g_mh[BATCH * DHEAD * DHEAD];   // M^T (fp16, [b][d][k])
__device__ __half g_xh[(size_t)ROWS * DIMK];     // 32 MB  x in fp16
__device__ __half g_ch[(size_t)ROWS * DIMK];     // 32 MB  context in fp16
__device__ __half g_wqh[(size_t)DIMK * DIMK];    // 8 MB   Wq fp16 [n][k]
__device__ __half g_wkvh[(size_t)256 * DIMK];    // 1 MB   [Wk;Wv] fp16
__device__ float  g_biaskv[256];

typedef unsigned long long u64;

// ------------------------- helpers ------------------------------------------
__device__ __forceinline__ uint32_t smem_u32(const void* p) {
    uint32_t a;
    asm("{ .reg .u64 t; cvta.to.shared.u64 t, %1; cvt.u32.u64 %0, t; }" : "=r"(a) : "l"(p));
    return a;
}
__device__ __forceinline__ void cp_async16(uint32_t saddr, const void* gaddr) {
    asm volatile("cp.async.ca.shared.global [%0], [%1], 16;" :: "r"(saddr), "l"(gaddr));
}
#define CP_COMMIT()  asm volatile("cp.async.commit_group;" ::: "memory")
#define CP_WAIT0()   asm volatile("cp.async.wait_group 0;" ::: "memory")

__device__ __forceinline__ void mma16816(float* c, const uint32_t* a, const uint32_t* b) {
    asm volatile(
        "mma.sync.aligned.m16n8k16.row.col.f32.f16.f16.f32 "
        "{%0,%1,%2,%3}, {%4,%5,%6,%7}, {%8,%9}, {%0,%1,%2,%3};"
        : "+f"(c[0]), "+f"(c[1]), "+f"(c[2]), "+f"(c[3])
        : "r"(a[0]), "r"(a[1]), "r"(a[2]), "r"(a[3]), "r"(b[0]), "r"(b[1]));
}
__device__ __forceinline__ void ldsm_x4(uint32_t* r, uint32_t addr) {
    asm volatile("ldmatrix.sync.aligned.m8n8.x4.shared.b16 {%0,%1,%2,%3}, [%4];"
                 : "=r"(r[0]), "=r"(r[1]), "=r"(r[2]), "=r"(r[3]) : "r"(addr));
}

// ------------------------- fused staging kernel ------------------------------
__global__ void tohalf_all(const float* __restrict__ x, const float* __restrict__ ctx,
                           const float* __restrict__ Wq, const float* __restrict__ Wk,
                           const float* __restrict__ Wv, const float* __restrict__ bk,
                           const float* __restrict__ bv)
{
    const int bid = blockIdx.x;
    if (bid == 18688) {
        if (threadIdx.x < 128) {
            g_biaskv[threadIdx.x] = bk[threadIdx.x];
            g_biaskv[threadIdx.x + 128] = bv[threadIdx.x];
        }
        return;
    }
    const float* src;
    __half* dst;
    int lb;
    if (bid < 8192)        { src = x;   dst = g_xh;  lb = bid; }
    else if (bid < 16384)  { src = ctx; dst = g_ch;  lb = bid - 8192; }
    else if (bid < 18432)  { src = Wq;  dst = g_wqh; lb = bid - 16384; }
    else if (bid < 18560)  { src = Wk;  dst = g_wkvh; lb = bid - 18432; }
    else                   { src = Wv;  dst = g_wkvh + (size_t)128 * DIMK; lb = bid - 18560; }
    size_t idx = ((size_t)lb * 256 + threadIdx.x) * 8;
    float4 x0 = *(const float4*)(src + idx);
    float4 x1 = *(const float4*)(src + idx + 4);
    __half2 h[4];
    h[0] = __floats2half2_rn(x0.x, x0.y);
    h[1] = __floats2half2_rn(x0.z, x0.w);
    h[2] = __floats2half2_rn(x1.x, x1.y);
    h[3] = __floats2half2_rn(x1.z, x1.w);
    *(uint4*)(dst + idx) = *(uint4*)h;
}

// ------------------------- HMMA fp16 GEMM + fused row-l2norm ----------------
// Single-barrier double-buffered pipeline:
//   top of iter: CP_WAIT0 (group committed LAST iter -> buf complete), barrier,
//   then prefetch nbuf (commit), then MMA on buf. One barrier per k-iter.
#define PITCH 40

__global__ __launch_bounds__(256, 2)
void gemm_f16(const __half* __restrict__ A, const __half* __restrict__ B,
              const float* __restrict__ bias, float* __restrict__ Cf,
              __half* __restrict__ Ch, int ldc, int normBlocks, float normScale)
{
    __shared__ __align__(16) __half As[2][128][PITCH];
    __shared__ __align__(16) __half Bs[2][128][PITCH];

    const int tid  = threadIdx.x;
    const int wid  = tid >> 5;
    const int lane = tid & 31;
    const int g    = lane >> 2;
    const int t    = lane & 3;
    const int warp_m = wid & 1;     // 64 rows
    const int warp_n = wid >> 1;    // 32 cols
    const int m0 = blockIdx.y << 7;
    const int n0 = blockIdx.x << 7;

    const __half* aBase = A + (size_t)m0 * DIMK;
    const __half* bBase = B + (size_t)n0 * DIMK;

    const int r0 = tid >> 2,          c0 = (tid & 3) << 3;
    const int r1 = (tid + 256) >> 2,  c1 = c0;

    const int lrow = lane & 15;
    const int lcol = (lane >> 4) << 3;

    float acc[4][4][4];
    #pragma unroll
    for (int i = 0; i < 4; i++)
        #pragma unroll
        for (int j = 0; j < 4; j++)
            #pragma unroll
            for (int k = 0; k < 4; k++) acc[i][j][k] = 0.f;

    cp_async16(smem_u32(&As[0][r0][c0]), aBase + (size_t)r0 * DIMK + c0);
    cp_async16(smem_u32(&As[0][r1][c1]), aBase + (size_t)r1 * DIMK + c1);
    cp_async16(smem_u32(&Bs[0][r0][c0]), bBase + (size_t)r0 * DIMK + c0);
    cp_async16(smem_u32(&Bs[0][r1][c1]), bBase + (size_t)r1 * DIMK + c1);
    CP_COMMIT();

    const int NT = DIMK / 32;   // 64
    const int mb = warp_m << 6;
    const int nb = warp_n << 5;

    for (int it = 0; it < NT; ++it) {
        const int buf = it & 1;
        CP_WAIT0();         // buf's group (committed prev iter / prologue) done
        __syncthreads();    // publish buf; orders prev-iter reads of nbuf
                            // before this iter's writes into nbuf

        if (it + 1 < NT) {
            const int nbuf = buf ^ 1;
            const int ko = (it + 1) << 5;
            cp_async16(smem_u32(&As[nbuf][r0][c0]), aBase + (size_t)r0 * DIMK + ko + c0);
            cp_async16(smem_u32(&As[nbuf][r1][c1]), aBase + (size_t)r1 * DIMK + ko + c1);
            cp_async16(smem_u32(&Bs[nbuf][r0][c0]), bBase + (size_t)r0 * DIMK + ko + c0);
            cp_async16(smem_u32(&Bs[nbuf][r1][c1]), bBase + (size_t)r1 * DIMK + ko + c1);
            CP_COMMIT();
        }

        #pragma unroll
        for (int ks = 0; ks < 2; ++ks) {
            const int kof = (ks << 4) + lcol;
            uint32_t bf[4][2];
            {
                uint32_t r[4];
                ldsm_x4(r, smem_u32(&Bs[buf][nb + lrow][kof]));
                bf[0][0] = r[0]; bf[1][0] = r[1]; bf[0][1] = r[2]; bf[1][1] = r[3];
                ldsm_x4(r, smem_u32(&Bs[buf][nb + 16 + lrow][kof]));
                bf[2][0] = r[0]; bf[3][0] = r[1]; bf[2][1] = r[2]; bf[3][1] = r[3];
            }
            #pragma unroll
            for (int mt = 0; mt < 4; ++mt) {
                uint32_t af[4];
                ldsm_x4(af, smem_u32(&As[buf][mb + (mt << 4) + lrow][kof]));
                #pragma unroll
                for (int nt = 0; nt < 4; ++nt)
                    mma16816(acc[mt][nt], af, bf[nt]);
            }
        }
        // no bottom barrier: next iteration's top barrier provides the ordering
    }
    __syncthreads();   // all MMA reads done before epilogue reuses As[0]

    // ---- epilogue: +bias, optional row l2norm, write fp16 or fp32 ----
    #pragma unroll
    for (int mt = 0; mt < 4; ++mt) {
        #pragma unroll
        for (int nt = 0; nt < 4; ++nt) {
            const int col = n0 + nb + (nt << 3) + (t << 1);
            const float b0 = bias[col], b1 = bias[col + 1];
            acc[mt][nt][0] += b0; acc[mt][nt][1] += b1;
            acc[mt][nt][2] += b0; acc[mt][nt][3] += b1;
        }
    }

    if (blockIdx.x < (unsigned)normBlocks) {
        float* red = (float*)&As[0][0][0];
        #pragma unroll
        for (int mt = 0; mt < 4; ++mt) {
            float s0 = 0.f, s1 = 0.f;
            #pragma unroll
            for (int nt = 0; nt < 4; ++nt) {
                s0 += acc[mt][nt][0] * acc[mt][nt][0] + acc[mt][nt][1] * acc[mt][nt][1];
                s1 += acc[mt][nt][2] * acc[mt][nt][2] + acc[mt][nt][3] * acc[mt][nt][3];
            }
            s0 += __shfl_xor_sync(0xffffffffu, s0, 1);
            s0 += __shfl_xor_sync(0xffffffffu, s0, 2);
            s1 += __shfl_xor_sync(0xffffffffu, s1, 1);
            s1 += __shfl_xor_sync(0xffffffffu, s1, 2);
            if (t == 0) {
                red[(mb + (mt << 4) + g) * 4 + warp_n]     = s0;
                red[(mb + (mt << 4) + g + 8) * 4 + warp_n] = s1;
            }
        }
        __syncthreads();
        #pragma unroll
        for (int mt = 0; mt < 4; ++mt) {
            const int rl = mb + (mt << 4) + g;
            float ssq0 = red[rl * 4] + red[rl * 4 + 1] + red[rl * 4 + 2] + red[rl * 4 + 3];
            float ssq1 = red[(rl + 8) * 4] + red[(rl + 8) * 4 + 1]
                       + red[(rl + 8) * 4 + 2] + red[(rl + 8) * 4 + 3];
            float inv0 = normScale / fmaxf(sqrtf(ssq0), 1e-12f);
            float inv1 = normScale / fmaxf(sqrtf(ssq1), 1e-12f);
            #pragma unroll
            for (int nt = 0; nt < 4; ++nt) {
                acc[mt][nt][0] *= inv0; acc[mt][nt][1] *= inv0;
                acc[mt][nt][2] *= inv1; acc[mt][nt][3] *= inv1;
            }
        }
    }

    #pragma unroll
    for (int mt = 0; mt < 4; ++mt) {
        const int row = m0 + mb + (mt << 4) + g;
        #pragma unroll
        for (int nt = 0; nt < 4; ++nt) {
            const int col = n0 + nb + (nt << 3) + (t << 1);
            if (Ch) {
                *(__half2*)(Ch + (size_t)row * ldc + col) =
                    __floats2half2_rn(acc[mt][nt][0], acc[mt][nt][1]);
                *(__half2*)(Ch + (size_t)(row + 8) * ldc + col) =
                    __floats2half2_rn(acc[mt][nt][2], acc[mt][nt][3]);
            } else {
                *(float2*)(Cf + (size_t)row * ldc + col) =
                    make_float2(acc[mt][nt][0], acc[mt][nt][1]);
                *(float2*)(Cf + (size_t)(row + 8) * ldc + col) =
                    make_float2(acc[mt][nt][2], acc[mt][nt][3]);
            }
        }
    }
}

// ------------------------- fp32 ktv (64-row chunks) --------------------------
__device__ __forceinline__ u64 pk2(float lo, float hi) {
    u64 r; asm("mov.b64 %0, {%1, %2};" : "=l"(r) : "f"(lo), "f"(hi)); return r;
}
__device__ __forceinline__ float2 upk2(u64 v) {
    float2 r; asm("mov.b64 {%0, %1}, %2;" : "=f"(r.x), "=f"(r.y) : "l"(v)); return r;
}
#define FMA2(acc, a, b) \
    asm("fma.rn.f32x2 %0, %1, %2, %0;" : "+l"(acc) : "l"(a), "l"(b))

__global__ void zero_m()
{
    int i = blockIdx.x * blockDim.x + threadIdx.x;
    reinterpret_cast<float4*>(g_m)[i] = make_float4(0.f, 0.f, 0.f, 0.f);
}

__global__ __launch_bounds__(256, 2)
void ktv_kernel(const float* __restrict__ KV, float* __restrict__ Mout)
{
    __shared__ float Ks[16][128];
    __shared__ float Vs[16][128];
    const int tid = threadIdx.x;
    const int tx = tid & 15;
    const int ty = tid >> 4;
    const int b = blockIdx.x;
    const int mbase = b * SEQ + blockIdx.y * 64;
    const float* kp = KV + (size_t)mbase * 256;
    const int lr = tid >> 4;
    const int lc = (tid & 15) << 3;

    u64 acc[8][4];
    #pragma unroll
    for (int i = 0; i < 8; i++)
        #pragma unroll
        for (int j = 0; j < 4; j++) acc[i][j] = 0ull;

    for (int mt = 0; mt < 64; mt += 16) {
        float4 k0 = *(const float4*)(kp + (size_t)(mt + lr) * 256 + lc);
        float4 k1 = *(const float4*)(kp + (size_t)(mt + lr) * 256 + lc + 4);
        float4 v0 = *(const float4*)(kp + 128 + (size_t)(mt + lr) * 256 + lc);
        float4 v1 = *(const float4*)(kp + 128 + (size_t)(mt + lr) * 256 + lc + 4);
        __syncthreads();
        *(float4*)&Ks[lr][lc] = k0; *(float4*)&Ks[lr][lc + 4] = k1;
        *(float4*)&Vs[lr][lc] = v0; *(float4*)&Vs[lr][lc + 4] = v1;
        __syncthreads();
        #pragma unroll
        for (int kk = 0; kk < 16; kk++) {
            float4 af0 = *(const float4*)&Ks[kk][ty << 2];
            float4 af1 = *(const float4*)&Ks[kk][64 + (ty << 2)];
            float4 bf0 = *(const float4*)&Vs[kk][tx << 2];
            float4 bf1 = *(const float4*)&Vs[kk][64 + (tx << 2)];
            u64 b2[4] = {pk2(bf0.x, bf0.y), pk2(bf0.z, bf0.w),
                         pk2(bf1.x, bf1.y), pk2(bf1.z, bf1.w)};
            float av[8] = {af0.x, af0.y, af0.z, af0.w, af1.x, af1.y, af1.z, af1.w};
            #pragma unroll
            for (int i = 0; i < 8; i++) {
                u64 a2 = pk2(av[i], av[i]);
                FMA2(acc[i][0], a2, b2[0]);
                FMA2(acc[i][1], a2, b2[1]);
                FMA2(acc[i][2], a2, b2[2]);
                FMA2(acc[i][3], a2, b2[3]);
            }
        }
    }
    float* Mb = Mout + b * (DHEAD * DHEAD);
    #pragma unroll
    for (int i = 0; i < 8; i++) {
        int row = (i < 4) ? (ty * 4 + i) : (64 + ty * 4 + i - 4);
        #pragma unroll
        for (int jp = 0; jp < 4; jp++) {
            int col = (jp < 2) ? (tx * 4 + jp * 2) : (64 + tx * 4 + (jp - 2) * 2);
            float2 v = upk2(acc[i][jp]);
            atomicAdd(&Mb[row * DHEAD + col],     v.x);
            atomicAdd(&Mb[row * DHEAD + col + 1], v.y);
        }
    }
}

// ------------------------- M split (hi only, transposed) ---------------------
__global__ void splitM(const float* __restrict__ M, __half* __restrict__ Mhi)
{
    int i = blockIdx.x * 256 + threadIdx.x;
    int b = i >> 14;
    int d = (i >> 7) & 127;
    int k = i & 127;
    Mhi[i] = __float2half_rn(M[(b << 14) + (k << 7) + d]);
}

// ------------------------- out = q16 @ Mh (single pass) ----------------------
#define PITCH2 136
#define QM_AS_BYTES (128 * PITCH2 * 2)
#define QM_SMEM (2 * QM_AS_BYTES)

__global__ __launch_bounds__(256)
void gemm_qm16(const __half* __restrict__ Q, const __half* __restrict__ Mhi,
               float* __restrict__ Out)
{
    extern __shared__ char dsm[];
    __half (*As)[PITCH2] = (__half(*)[PITCH2])dsm;
    __half (*Bs)[PITCH2] = (__half(*)[PITCH2])(dsm + QM_AS_BYTES);

    const int tid  = threadIdx.x;
    const int wid  = tid >> 5;
    const int lane = tid & 31;
    const int g    = lane >> 2;
    const int t    = lane & 3;
    const int warp_m = wid & 1;
    const int warp_n = wid >> 1;
    const int m0 = blockIdx.x << 7;
    const int h  = blockIdx.y;
    const int b  = m0 >> 11;

    const __half* qBase = Q + (size_t)m0 * DIMK + h * DHEAD;
    const __half* mh = Mhi + (b << 14);

    #pragma unroll
    for (int p = 0; p < 8; ++p) {
        int id = p * 256 + tid;
        int r = id >> 4, cch = (id & 15) << 3;
        *(uint4*)&As[r][cch] = *(const uint4*)(qBase + (size_t)r * DIMK + cch);
        *(uint4*)&Bs[r][cch] = *(const uint4*)(mh + r * 128 + cch);
    }
    __syncthreads();

    float acc[4][4][4];
    #pragma unroll
    for (int i = 0; i < 4; i++)
        #pragma unroll
        for (int j = 0; j < 4; j++)
            #pragma unroll
            for (int k = 0; k < 4; k++) acc[i][j][k] = 0.f;

    const int mb = warp_m << 6;
    const int nb = warp_n << 5;

    #pragma unroll
    for (int ks = 0; ks < 8; ++ks) {
        const int kof = (ks << 4) + (t << 1);
        uint32_t bf[4][2];
        #pragma unroll
        for (int nt = 0; nt < 4; ++nt) {
            bf[nt][0] = *(const uint32_t*)&Bs[nb + (nt << 3) + g][kof];
            bf[nt][1] = *(const uint32_t*)&Bs[nb + (nt << 3) + g][kof + 8];
        }
        #pragma unroll
        for (int mt = 0; mt < 4; ++mt) {
            uint32_t af[4];
            af[0] = *(const uint32_t*)&As[mb + (mt << 4) + g][kof];
            af[1] = *(const uint32_t*)&As[mb + (mt << 4) + g + 8][kof];
            af[2] = *(const uint32_t*)&As[mb + (mt << 4) + g][kof + 8];
            af[3] = *(const uint32_t*)&As[mb + (mt << 4) + g + 8][kof + 8];
            #pragma unroll
            for (int nt = 0; nt < 4; ++nt)
                mma16816(acc[mt][nt], af, bf[nt]);
        }
    }

    float* obase = Out + ((size_t)(b * HEADS + h) * SEQ) * DHEAD;
    #pragma unroll
    for (int mt = 0; mt < 4; ++mt) {
        const int nn0 = (m0 + mb + (mt << 4) + g) & (SEQ - 1);
        #pragma unroll
        for (int nt = 0; nt < 4; ++nt) {
            const int d = nb + (nt << 3) + (t << 1);
            *(float2*)(obase + (size_t)nn0 * DHEAD + d) =
                make_float2(acc[mt][nt][0], acc[mt][nt][1]);
            *(float2*)(obase + (size_t)(nn0 + 8) * DHEAD + d) =
                make_float2(acc[mt][nt][2], acc[mt][nt][3]);
        }
    }
}

// ---------------------------------------------------------------------------
extern "C" void kernel_launch(void* const* d_in, const int* in_sizes, int n_in,
                              void* d_out, int out_size)
{
    const float* x       = (const float*)d_in[0];
    const float* context = (const float*)d_in[1];
    const float* Wq      = (const float*)d_in[2];
    const float* bq      = (const float*)d_in[3];
    const float* Wk      = (const float*)d_in[4];
    const float* bk      = (const float*)d_in[5];
    const float* Wv      = (const float*)d_in[6];
    const float* bv      = (const float*)d_in[7];
    float* out = (float*)d_out;

    float *kv, *m, *biaskv;
    __half *qh, *mh, *xh, *ch, *wqh, *wkvh;
    cudaGetSymbolAddress((void**)&qh,  g_qh);
    cudaGetSymbolAddress((void**)&kv,  g_kv);
    cudaGetSymbolAddress((void**)&m,   g_m);
    cudaGetSymbolAddress((void**)&mh,  g_mh);
    cudaGetSymbolAddress((void**)&xh,  g_xh);
    cudaGetSymbolAddress((void**)&ch,  g_ch);
    cudaGetSymbolAddress((void**)&wqh, g_wqh);
    cudaGetSymbolAddress((void**)&wkvh, g_wkvh);
    cudaGetSymbolAddress((void**)&biaskv, g_biaskv);

    cudaFuncSetAttribute(gemm_qm16, cudaFuncAttributeMaxDynamicSharedMemorySize, QM_SMEM);

    // fork/join resources (host-side objects; created per capture call,
    // intentionally not destroyed while the capture references them)
    cudaStream_t sB;
    cudaStreamCreateWithFlags(&sB, cudaStreamNonBlocking);
    cudaEvent_t evStage, evB;
    cudaEventCreateWithFlags(&evStage, cudaEventDisableTiming);
    cudaEventCreateWithFlags(&evB, cudaEventDisableTiming);

    // 1) fused staging (origin stream)
    tohalf_all<<<18689, 256>>>(x, context, Wq, Wk, Wv, bk, bv);
    cudaEventRecord(evStage, 0);

    // ---- branch B (side stream): kv -> zero -> ktv -> splitM ----
    cudaStreamWaitEvent(sB, evStage, 0);
    gemm_f16<<<dim3(2, ROWS / 128), 256, 0, sB>>>(
        ch, wkvh, biaskv, kv, nullptr, 256, 1, 1.0f);
    zero_m<<<64, 256, 0, sB>>>();
    ktv_kernel<<<dim3(BATCH, 32), 256, 0, sB>>>(kv, m);
    splitM<<<256, 256, 0, sB>>>(m, mh);
    cudaEventRecord(evB, sB);

    // ---- branch A (origin stream): q projection + fused l2norm ----
    gemm_f16<<<dim3(DIMK / 128, ROWS / 128), 256>>>(
        xh, wqh, bq, nullptr, qh, DIMK, 16, 0.08838834764831845f);

    // ---- join, then Out = Qn @ M[b] ----
    cudaStreamWaitEvent(0, evB, 0);
    gemm_qm16<<<dim3(ROWS / 128, HEADS), 256, QM_SMEM>>>(qh, mh, out);
}